// round 17
// baseline (speedup 1.0000x reference)
#include <cuda_runtime.h>
#include <cuda_bf16.h>
#include <cstdint>

#define B_    512
#define T_    128
#define ID_   128
#define HD_   256
#define G4_   1024
#define OUTD_ 128
#define BT_   65536

typedef unsigned long long ull;

// ---------------- scratch ----------------
__device__ ull g_Wb[2][16][16][8][32][2];   // [dir][kt][w][nt][lane][pl] b-frag pairs, 2MB
__device__ float g_Wip[2][ID_][G4_];        // Wi, permuted cols colp = dim*4+g
__device__ float g_bpp[2][G4_];
__device__ float g_gx[2][(size_t)BT_ * G4_];
__device__ float g_x1[(size_t)B_ * T_ * 2 * HD_];
__device__ float g_x2[(size_t)B_ * T_ * HD_];
__device__ float g_x3[(size_t)B_ * T_ * HD_];
__device__ float g_x4[(size_t)B_ * T_ * OUTD_];

// ---------------- helpers ----------------
__device__ __forceinline__ ull fma2(ull a, ull b, ull c) {
    ull d; asm("fma.rn.f32x2 %0, %1, %2, %3;" : "=l"(d) : "l"(a), "l"(b), "l"(c)); return d;
}
__device__ __forceinline__ ull dupf(float v) {
    ull r; unsigned u = __float_as_uint(v);
    asm("mov.b64 %0, {%1, %1};" : "=l"(r) : "r"(u)); return r;
}
__device__ __forceinline__ float lo32(ull v) { return __uint_as_float((unsigned)v); }
__device__ __forceinline__ float hi32(ull v) { return __uint_as_float((unsigned)(v >> 32)); }
__device__ __forceinline__ float sigm(float x) { return 1.f / (1.f + __expf(-x)); }
__device__ __forceinline__ float tanhp(float x) { return fmaf(2.f, sigm(2.f * x), -1.f); }
__device__ __forceinline__ unsigned pack_hi2(float a, float b) {
    unsigned ua = __bfloat16_as_ushort(__float2bfloat16(a));
    unsigned ub = __bfloat16_as_ushort(__float2bfloat16(b));
    return ua | (ub << 16);
}
__device__ __forceinline__ unsigned pack_lo2(float a, float b) {
    __nv_bfloat16 ha = __float2bfloat16(a), hb = __float2bfloat16(b);
    unsigned ua = __bfloat16_as_ushort(__float2bfloat16(a - __bfloat162float(ha)));
    unsigned ub = __bfloat16_as_ushort(__float2bfloat16(b - __bfloat162float(hb)));
    return ua | (ub << 16);
}
__device__ __forceinline__ float bf2f(unsigned u16) { return __uint_as_float(u16 << 16); }

#define MMA_BF16(d, a, b) \
    asm volatile("mma.sync.aligned.m16n8k16.row.col.f32.bf16.bf16.f32 " \
        "{%0,%1,%2,%3}, {%4,%5,%6,%7}, {%8,%9}, {%0,%1,%2,%3};" \
        : "+f"((d)[0]), "+f"((d)[1]), "+f"((d)[2]), "+f"((d)[3]) \
        : "r"((a)[0]), "r"((a)[1]), "r"((a)[2]), "r"((a)[3]), "r"((b)[0]), "r"((b)[1]))

// ---------------- prep: pack streamed B-frags (full Wh), Wip + bias ----------------
__global__ void prep_kernel(const float* __restrict__ Wh_f, const float* __restrict__ Wh_r,
                            const float* __restrict__ Wi_f, const float* __restrict__ Wi_r,
                            const float* __restrict__ bi_f, const float* __restrict__ bh_f,
                            const float* __restrict__ bi_r, const float* __restrict__ bh_r) {
    int idx = blockIdx.x * blockDim.x + threadIdx.x;
    int stride = gridDim.x * blockDim.x;
    // g_Wb[dir][kt][w][nt][lane][pl]: ull = (pr0 u32 | pr1 u32 << 32)
    const int wbt = 2 * 16 * 16 * 8 * 32 * 2;
    ull* wbf = &g_Wb[0][0][0][0][0][0];
    for (int i = idx; i < wbt; i += stride) {
        int pl = i & 1;
        int lane = (i >> 1) & 31;
        int nt = (i >> 6) & 7;
        int w = (i >> 9) & 15;
        int kt = (i >> 13) & 15;
        int dir = (i >> 17) & 1;
        int n = w * 64 + nt * 8 + (lane >> 2);
        int sc = (n & 3) * 256 + (n >> 2);          // gate*256 + dim
        int k0 = kt * 16 + (lane & 3) * 2;
        const float* Wh = dir ? Wh_r : Wh_f;
        float a0 = Wh[k0 * G4_ + sc],       a1 = Wh[(k0 + 1) * G4_ + sc];
        float b0 = Wh[(k0 + 8) * G4_ + sc], b1 = Wh[(k0 + 9) * G4_ + sc];
        unsigned u0 = pl ? pack_lo2(a0, a1) : pack_hi2(a0, a1);
        unsigned u1 = pl ? pack_lo2(b0, b1) : pack_hi2(b0, b1);
        wbf[i] = (ull)u0 | ((ull)u1 << 32);
    }
    const int witotal = 2 * ID_ * G4_;
    for (int i = idx; i < witotal; i += stride) {
        int dir = i / (ID_ * G4_), r = i % (ID_ * G4_);
        int k = r >> 10, colp = r & 1023;
        int dim = colp >> 2, g = colp & 3;
        const float* Wi = dir ? Wi_r : Wi_f;
        g_Wip[dir][k][colp] = Wi[k * G4_ + g * 256 + dim];
    }
    for (int i = idx; i < 2 * G4_; i += stride) {
        int dir = i >> 10, colp = i & 1023;
        int sc = (colp & 3) * 256 + (colp >> 2);
        g_bpp[dir][colp] = dir ? (bi_r[sc] + bh_r[sc]) : (bi_f[sc] + bh_f[sc]);
    }
}

// ---------------- sync-free recurrent LSTM ----------------
// 64 CTAs x 512 thr, NO clusters, NO inter-CTA sync. bid: dir = bid>>5, rows (bid&31)*16..+16.
// CTA computes ALL 1024 gate cols for its 16 rows; h lives in 17KB smem staging.
// Warp w = m16 x n64 (dims w*16..+16, gate-interleaved). Wh streamed from L2 (2MB resident),
// register double-buffered, R13-verified fragment layouts.
__global__ __launch_bounds__(512, 1) void lstm_kernel() {
    __shared__ __align__(16) unsigned short smA[2][16][264];   // [plane hi/lo][row][dim]

    const int tid = threadIdx.x, lane = tid & 31, w = tid >> 5;
    const int dir = blockIdx.x >> 5, b0 = (blockIdx.x & 31) * 16;
    const int gid = lane >> 2, m = lane & 3;
    const int row_eff = gid + ((lane & 1) ? 8 : 0);
    const int dlbit = (lane >> 1) & 1;

    // zero staging (h(0) = 0)
    for (int i = tid; i < 2 * 16 * 264; i += 512) (&smA[0][0][0])[i] = 0;

    const ulonglong2* wb = (const ulonglong2*)&g_Wb[dir][0][w][0][0][0] + lane;
    // strides (ulonglong2): nt 32, kt 4096
    const float* gx0 = &g_gx[dir][0] + ((size_t)(b0 + row_eff) * T_) * G4_ + w * 64 + dlbit * 4;

    float cst[8];
#pragma unroll
    for (int j = 0; j < 8; j++) cst[j] = 0.f;
    __syncthreads();

#pragma unroll 1
    for (int t = 0; t < T_; t++) {
        const int ts = dir ? (T_ - 1 - t) : t;

        ulonglong2 bb[2][8];
#pragma unroll
        for (int nt = 0; nt < 8; nt++) bb[0][nt] = wb[nt * 32];

        float d[8][4];
#pragma unroll
        for (int nt = 0; nt < 8; nt++)
#pragma unroll
            for (int j = 0; j < 4; j++) d[nt][j] = 0.f;

#pragma unroll 1
        for (int kt = 0; kt < 16; kt++) {
            const int cur = kt & 1;
            if (kt < 15) {
#pragma unroll
                for (int nt = 0; nt < 8; nt++)
                    bb[cur ^ 1][nt] = wb[(size_t)(kt + 1) * 4096 + nt * 32];
            }
            unsigned ah[4], al[4];
            const char* ab = (const char*)&smA[0][0][0] + gid * 528 + m * 4 + kt * 32;
            ah[0] = *(const unsigned*)ab;
            ah[1] = *(const unsigned*)(ab + 8 * 528);
            ah[2] = *(const unsigned*)(ab + 16);
            ah[3] = *(const unsigned*)(ab + 8 * 528 + 16);
            al[0] = *(const unsigned*)(ab + 8448);
            al[1] = *(const unsigned*)(ab + 8448 + 8 * 528);
            al[2] = *(const unsigned*)(ab + 8448 + 16);
            al[3] = *(const unsigned*)(ab + 8448 + 8 * 528 + 16);
#pragma unroll
            for (int nt = 0; nt < 8; nt++) {
                unsigned bh[2], bl[2];
                bh[0] = (unsigned)bb[cur][nt].x; bh[1] = (unsigned)(bb[cur][nt].x >> 32);
                bl[0] = (unsigned)bb[cur][nt].y; bl[1] = (unsigned)(bb[cur][nt].y >> 32);
                MMA_BF16(d[nt], ah, bh);
                MMA_BF16(d[nt], al, bh);
                MMA_BF16(d[nt], ah, bl);
            }
        }

        // gx loads (post-MMA: frees registers; one exposed L2/DRAM latency per step)
        float4 gxv[8];
        {
            const float* gp = gx0 + (size_t)ts * G4_;
#pragma unroll
            for (int nt = 0; nt < 8; nt++) gxv[nt] = *(const float4*)(gp + nt * 8);
        }

        // cell update (shuffle-pair, R13-verified)
        float hv[8];
#pragma unroll
        for (int nt = 0; nt < 8; nt++) {
            float s0 = __shfl_xor_sync(0xffffffffu, d[nt][0], 1);
            float s1 = __shfl_xor_sync(0xffffffffu, d[nt][1], 1);
            float s2 = __shfl_xor_sync(0xffffffffu, d[nt][2], 1);
            float s3 = __shfl_xor_sync(0xffffffffu, d[nt][3], 1);
            float gf, gi, ga, go;
            if (lane & 1) { gf = s2; gi = s3; ga = d[nt][2]; go = d[nt][3]; }
            else          { gf = d[nt][0]; gi = d[nt][1]; ga = s0; go = s1; }
            gf += gxv[nt].x; gi += gxv[nt].y; ga += gxv[nt].z; go += gxv[nt].w;
            float f = sigm(gf), ii = sigm(gi), a = tanhp(ga), o = sigm(go);
            float cc = fmaf(f, cst[nt], ii * a);
            cst[nt] = cc;
            hv[nt] = o * tanhp(cc);
        }

        __syncthreads();   // all A reads of step t done
        // write h(t+1) staging (hi/lo planes)
#pragma unroll
        for (int nt = 0; nt < 8; nt++) {
            int dg = w * 16 + 2 * nt + dlbit;
            float v = hv[nt];
            __nv_bfloat16 hb = __float2bfloat16(v);
            smA[0][row_eff][dg] = __bfloat16_as_ushort(hb);
            smA[1][row_eff][dg] =
                __bfloat16_as_ushort(__float2bfloat16(v - __bfloat162float(hb)));
        }
        __syncthreads();   // staging ready for next step + writeout

        // coalesced x1 writeout: thread = (row tid>>5, dims lane*8..+8), reconstruct hi+lo
        {
            int r = tid >> 5, d0 = lane * 8;
            const unsigned* hp = (const unsigned*)&smA[0][r][d0];
            const unsigned* lp = (const unsigned*)&smA[1][r][d0];
            float f[8];
#pragma unroll
            for (int i = 0; i < 4; i++) {
                unsigned h = hp[i], l = lp[i];
                f[2 * i]     = bf2f(h & 0xffffu) + bf2f(l & 0xffffu);
                f[2 * i + 1] = bf2f(h >> 16)     + bf2f(l >> 16);
            }
            float* xp = g_x1 + ((size_t)(b0 + r) * T_ + t) * 512 + dir * 256 + d0;
            *(float4*)xp = make_float4(f[0], f[1], f[2], f[3]);
            *(float4*)(xp + 4) = make_float4(f[4], f[5], f[6], f[7]);
        }
    }
}

// ---------------- fp32x2 GEMM with bias + optional leaky-relu ----------------
template <int ACT>
__global__ __launch_bounds__(256) void gemm_kernel(const float* __restrict__ A,
                                                   const float* __restrict__ W,
                                                   const float* __restrict__ bias,
                                                   float* __restrict__ C,
                                                   int M, int N, int K) {
    __shared__ __align__(16) float smA[16][64];
    __shared__ __align__(16) float smW[16][128];
    const int tid = threadIdx.x;
    const int n0 = blockIdx.x * 128, m0 = blockIdx.y * 64;
    const int col = (tid & 31) * 4, rg = (tid >> 5) * 8;
    ull acc[4][4];
#pragma unroll
    for (int rp = 0; rp < 4; rp++)
#pragma unroll
        for (int c = 0; c < 4; c++) acc[rp][c] = 0ull;
    const int la_r = tid >> 2, la_k = (tid & 3) * 4;
    const int lw_n = (tid & 31) * 4, lw_k = tid >> 5;
    for (int k0 = 0; k0 < K; k0 += 16) {
        float4 av = *(const float4*)&A[(size_t)(m0 + la_r) * K + k0 + la_k];
        smA[la_k + 0][la_r] = av.x; smA[la_k + 1][la_r] = av.y;
        smA[la_k + 2][la_r] = av.z; smA[la_k + 3][la_r] = av.w;
        *(float4*)&smW[lw_k][lw_n]     = *(const float4*)&W[(size_t)(k0 + lw_k) * N + n0 + lw_n];
        *(float4*)&smW[lw_k + 8][lw_n] = *(const float4*)&W[(size_t)(k0 + lw_k + 8) * N + n0 + lw_n];
        __syncthreads();
#pragma unroll
        for (int kk = 0; kk < 16; kk++) {
            float4 wv = *(const float4*)&smW[kk][col];
            ull wd0 = dupf(wv.x), wd1 = dupf(wv.y), wd2 = dupf(wv.z), wd3 = dupf(wv.w);
#pragma unroll
            for (int rp = 0; rp < 4; rp++) {
                ull hp = *(const ull*)&smA[kk][rg + 2 * rp];
                acc[rp][0] = fma2(hp, wd0, acc[rp][0]);
                acc[rp][1] = fma2(hp, wd1, acc[rp][1]);
                acc[rp][2] = fma2(hp, wd2, acc[rp][2]);
                acc[rp][3] = fma2(hp, wd3, acc[rp][3]);
            }
        }
        __syncthreads();
    }
    const float4 bv = *(const float4*)&bias[n0 + col];
#pragma unroll
    for (int rp = 0; rp < 4; rp++) {
        const int row0 = m0 + rg + 2 * rp;
        float4 v0, v1;
        v0.x = lo32(acc[rp][0]) + bv.x; v0.y = lo32(acc[rp][1]) + bv.y;
        v0.z = lo32(acc[rp][2]) + bv.z; v0.w = lo32(acc[rp][3]) + bv.w;
        v1.x = hi32(acc[rp][0]) + bv.x; v1.y = hi32(acc[rp][1]) + bv.y;
        v1.z = hi32(acc[rp][2]) + bv.z; v1.w = hi32(acc[rp][3]) + bv.w;
        if (ACT) {
            v0.x = fmaxf(v0.x, 0.1f * v0.x); v0.y = fmaxf(v0.y, 0.1f * v0.y);
            v0.z = fmaxf(v0.z, 0.1f * v0.z); v0.w = fmaxf(v0.w, 0.1f * v0.w);
            v1.x = fmaxf(v1.x, 0.1f * v1.x); v1.y = fmaxf(v1.y, 0.1f * v1.y);
            v1.z = fmaxf(v1.z, 0.1f * v1.z); v1.w = fmaxf(v1.w, 0.1f * v1.w);
        }
        *(float4*)&C[(size_t)row0 * N + n0 + col]       = v0;
        *(float4*)&C[(size_t)(row0 + 1) * N + n0 + col] = v1;
    }
}

// ---------------- head ----------------
__global__ __launch_bounds__(256) void head_kernel(float* __restrict__ out) {
    const int row = blockIdx.x * blockDim.x + threadIdx.x;
    if (row >= B_ * T_) return;
    const float* x = g_x4 + (size_t)row * OUTD_;
    float* o = out + (size_t)row * OUTD_;
#pragma unroll 4
    for (int j = 0; j < 64; j++) o[j] = sigm(x[j]);
    {
        float e[8], mx = -1e30f;
#pragma unroll
        for (int j = 0; j < 8; j++) { e[j] = x[64 + j]; mx = fmaxf(mx, e[j]); }
        float s = 0.f;
#pragma unroll
        for (int j = 0; j < 8; j++) { e[j] = __expf(e[j] - mx); s += e[j]; }
        float inv = 1.f / s;
#pragma unroll
        for (int j = 0; j < 8; j++) o[64 + j] = e[j] * inv;
    }
    {
        float e[16], mx = -1e30f;
#pragma unroll
        for (int j = 0; j < 16; j++) { e[j] = x[72 + j]; mx = fmaxf(mx, e[j]); }
        float s = 0.f;
#pragma unroll
        for (int j = 0; j < 16; j++) { e[j] = __expf(e[j] - mx); s += e[j]; }
        float inv = 1.f / s;
#pragma unroll
        for (int j = 0; j < 16; j++) o[72 + j] = e[j] * inv;
    }
    {
        float e[40], mx = -1e30f;
#pragma unroll
        for (int j = 0; j < 40; j++) { e[j] = x[88 + j]; mx = fmaxf(mx, e[j]); }
        float s = 0.f;
#pragma unroll
        for (int j = 0; j < 40; j++) { e[j] = __expf(e[j] - mx); s += e[j]; }
        float inv = 1.f / s;
#pragma unroll
        for (int j = 0; j < 40; j++) o[88 + j] = e[j] * inv;
    }
}

// ---------------- launch ----------------
extern "C" void kernel_launch(void* const* d_in, const int* in_sizes, int n_in,
                              void* d_out, int out_size) {
    (void)in_sizes; (void)n_in; (void)out_size;
    const float* x0   = (const float*)d_in[0];
    const float* Wi_f = (const float*)d_in[1];
    const float* bi_f = (const float*)d_in[2];
    const float* Wh_f = (const float*)d_in[3];
    const float* bh_f = (const float*)d_in[4];
    const float* Wi_r = (const float*)d_in[5];
    const float* bi_r = (const float*)d_in[6];
    const float* Wh_r = (const float*)d_in[7];
    const float* bh_r = (const float*)d_in[8];
    const float* W1   = (const float*)d_in[9];
    const float* b1   = (const float*)d_in[10];
    const float* W2   = (const float*)d_in[11];
    const float* b2   = (const float*)d_in[12];
    const float* W3   = (const float*)d_in[13];
    const float* b3   = (const float*)d_in[14];
    float* out = (float*)d_out;

    float *p_x1, *p_x2, *p_x3, *p_x4, *p_gx, *p_bpp, *p_wip;
    cudaGetSymbolAddress((void**)&p_x1, g_x1);
    cudaGetSymbolAddress((void**)&p_x2, g_x2);
    cudaGetSymbolAddress((void**)&p_x3, g_x3);
    cudaGetSymbolAddress((void**)&p_x4, g_x4);
    cudaGetSymbolAddress((void**)&p_gx, g_gx);
    cudaGetSymbolAddress((void**)&p_bpp, g_bpp);
    cudaGetSymbolAddress((void**)&p_wip, g_Wip);

    prep_kernel<<<256, 256>>>(Wh_f, Wh_r, Wi_f, Wi_r, bi_f, bh_f, bi_r, bh_r);

    gemm_kernel<0><<<dim3(G4_ / 128, BT_ / 64), 256>>>(x0, p_wip, p_bpp, p_gx, BT_, G4_, ID_);
    gemm_kernel<0><<<dim3(G4_ / 128, BT_ / 64), 256>>>(x0, p_wip + (size_t)ID_ * G4_, p_bpp + G4_,
                                                       p_gx + (size_t)BT_ * G4_, BT_, G4_, ID_);
    lstm_kernel<<<64, 512>>>();

    const int M = B_ * T_;
    gemm_kernel<1><<<dim3(HD_ / 128, M / 64), 256>>>(p_x1, W1, b1, p_x2, M, HD_, 2 * HD_);
    gemm_kernel<1><<<dim3(HD_ / 128, M / 64), 256>>>(p_x2, W2, b2, p_x3, M, HD_, HD_);
    gemm_kernel<0><<<dim3(OUTD_ / 128, M / 64), 256>>>(p_x3, W3, b3, p_x4, M, OUTD_, HD_);
    head_kernel<<<(M + 255) / 256, 256>>>(out);
}